// round 9
// baseline (speedup 1.0000x reference)
#include <cuda_runtime.h>
#include <cuda_bf16.h>

// out[b,c,t,l] = (x[b,c,i0,l] + x[b,c,i1,l] + x[b,c,i2,l]) / 3
// x: (32, 2, 24, 32768) fp32, out: (32, 2, 30, 32768) fp32
//
// R5 body (banded sliding window, <=7 float4 live, default loads,
// __stcs stores, TPB=256, 8 CTAs/SM) made persistent: exactly one wave of
// 148*8 = 1184 CTAs, grid-stride over the 2048 logical chunks. Removes the
// 73%-filled second wave + wave-transition overhead.

#define NV 24
#define NT 30
#define L  32768
#define L4 (L / 4)
#define TPB 256
#define NCHUNK (L4 / TPB * 64)   // 32 * 64 = 2048 logical chunks
#define NBLK 1184                // 148 SMs * 8 CTAs

__global__ __launch_bounds__(TPB, 8)
void tri_mean_kernel(const float4* __restrict__ x, float4* __restrict__ out) {
    const float s = 1.0f / 3.0f;

    for (int cid = blockIdx.x; cid < NCHUNK; cid += NBLK) {
        // Preserve R5's linear-bid mapping: colblock fastest, bc slow.
        const int colblock = cid & 31;          // cid % 32
        const int bc       = cid >> 5;          // cid / 32
        const int col      = colblock * TPB + threadIdx.x;

        const float4* __restrict__ xb = x   + (size_t)bc * NV * L4 + col;
        float4* __restrict__ ob       = out + (size_t)bc * NT * L4 + col;

#define LD(i)  xb[(size_t)(i) * L4]
#define EMIT(t, a, b, c) do {                        \
        float4 _r;                                   \
        _r.x = ((a).x + (b).x + (c).x) * s;          \
        _r.y = ((a).y + (b).y + (c).y) * s;          \
        _r.z = ((a).z + (b).z + (c).z) * s;          \
        _r.w = ((a).w + (b).w + (c).w) * s;          \
        __stcs(&ob[(size_t)(t) * L4], _r);           \
    } while (0)

        float4 A0, A1, A2, A3, B0, B1, B2, B3;

        // row0 (3): v0,v1,v2   row1 (4): v3,v4,v5,v6
        A0 = LD(0);  A1 = LD(1);  A2 = LD(2);
        B0 = LD(3);  B1 = LD(4);  B2 = LD(5);  B3 = LD(6);
        // band0: (0,3,4),(0,1,4),(1,4,5),(1,2,5),(2,5,6)
        EMIT(0, A0, B0, B1);
        EMIT(1, A0, A1, B1);
        EMIT(2, A1, B1, B2);
        EMIT(3, A1, A2, B2);
        EMIT(4, A2, B2, B3);

        // A = row1 (4), load row2 (3): v7,v8,v9
        A0 = B0; A1 = B1; A2 = B2; A3 = B3;
        B0 = LD(7);  B1 = LD(8);  B2 = LD(9);
        // band1: (3,4,7),(4,7,8),(4,5,8),(5,8,9),(5,6,9)
        EMIT(5, A0, A1, B0);
        EMIT(6, A1, B0, B1);
        EMIT(7, A1, A2, B1);
        EMIT(8, A2, B1, B2);
        EMIT(9, A2, A3, B2);

        // A = row2 (3), load row3 (4): v10..v13
        A0 = B0; A1 = B1; A2 = B2;
        B0 = LD(10); B1 = LD(11); B2 = LD(12); B3 = LD(13);
        // band2: (7,10,11),(7,8,11),(8,11,12),(8,9,12),(9,12,13)
        EMIT(10, A0, B0, B1);
        EMIT(11, A0, A1, B1);
        EMIT(12, A1, B1, B2);
        EMIT(13, A1, A2, B2);
        EMIT(14, A2, B2, B3);

        // A = row3 (4), load row4 (3): v14..v16
        A0 = B0; A1 = B1; A2 = B2; A3 = B3;
        B0 = LD(14); B1 = LD(15); B2 = LD(16);
        // band3: (10,11,14),(11,14,15),(11,12,15),(12,15,16),(12,13,16)
        EMIT(15, A0, A1, B0);
        EMIT(16, A1, B0, B1);
        EMIT(17, A1, A2, B1);
        EMIT(18, A2, B1, B2);
        EMIT(19, A2, A3, B2);

        // A = row4 (3), load row5 (4): v17..v20
        A0 = B0; A1 = B1; A2 = B2;
        B0 = LD(17); B1 = LD(18); B2 = LD(19); B3 = LD(20);
        // band4: (14,17,18),(14,15,18),(15,18,19),(15,16,19),(16,19,20)
        EMIT(20, A0, B0, B1);
        EMIT(21, A0, A1, B1);
        EMIT(22, A1, B1, B2);
        EMIT(23, A1, A2, B2);
        EMIT(24, A2, B2, B3);

        // A = row5 (4), load row6 (3): v21..v23
        A0 = B0; A1 = B1; A2 = B2; A3 = B3;
        B0 = LD(21); B1 = LD(22); B2 = LD(23);
        // band5: (17,18,21),(18,21,22),(18,19,22),(19,22,23),(19,20,23)
        EMIT(25, A0, A1, B0);
        EMIT(26, A1, B0, B1);
        EMIT(27, A1, A2, B1);
        EMIT(28, A2, B1, B2);
        EMIT(29, A2, A3, B2);

#undef LD
#undef EMIT
    }
}

extern "C" void kernel_launch(void* const* d_in, const int* in_sizes, int n_in,
                              void* d_out, int out_size) {
    const float4* x = (const float4*)d_in[0];
    float4* out = (float4*)d_out;

    dim3 block(TPB);
    dim3 grid(NBLK);   // 1184 = one full wave at 8 CTAs/SM
    tri_mean_kernel<<<grid, block>>>(x, out);
}

// round 10
// speedup vs baseline: 1.3868x; 1.3868x over previous
#include <cuda_runtime.h>
#include <cuda_bf16.h>

// out[b,c,t,l] = (x[b,c,i0,l] + x[b,c,i1,l] + x[b,c,i2,l]) / 3
// x: (32, 2, 24, 32768) fp32, out: (32, 2, 30, 32768) fp32
//
// R5 shape (TPB=256, grid (32,64), default loads, __stcs stores) with
// ONE-BAND-AHEAD prefetch: rows of band k+1 are loaded before band k's
// EMITs, so every warp keeps 3-4 reads in flight while storing -> deeper
// DRAM read queues, better read/write batching at the controllers.
// Live set ~11-12 float4 -> launch_bounds(256,4) (64-reg budget, no spill).

#define NV 24
#define NT 30
#define L  32768
#define L4 (L / 4)
#define TPB 256

__global__ __launch_bounds__(TPB, 4)
void tri_mean_kernel(const float4* __restrict__ x, float4* __restrict__ out) {
    const int col = blockIdx.x * TPB + threadIdx.x;   // 0 .. L4-1
    const int bc  = blockIdx.y;                       // 0 .. 63

    const float4* __restrict__ xb = x   + (size_t)bc * NV * L4 + col;
    float4* __restrict__ ob       = out + (size_t)bc * NT * L4 + col;

    const float s = 1.0f / 3.0f;

#define LD(i)  xb[(size_t)(i) * L4]
#define EMIT(t, a, b, c) do {                        \
        float4 _r;                                   \
        _r.x = ((a).x + (b).x + (c).x) * s;          \
        _r.y = ((a).y + (b).y + (c).y) * s;          \
        _r.z = ((a).z + (b).z + (c).z) * s;          \
        _r.w = ((a).w + (b).w + (c).w) * s;          \
        __stcs(&ob[(size_t)(t) * L4], _r);           \
    } while (0)

    float4 A0, A1, A2, A3;      // band's lower row
    float4 B0, B1, B2, B3;      // band's upper row
    float4 C0, C1, C2, C3;      // prefetched next row

    // Rows (start,size): r0(0,3) r1(3,4) r2(7,3) r3(10,4) r4(14,3) r5(17,4) r6(21,3)
    A0 = LD(0);  A1 = LD(1);  A2 = LD(2);              // row0
    B0 = LD(3);  B1 = LD(4);  B2 = LD(5);  B3 = LD(6); // row1
    C0 = LD(7);  C1 = LD(8);  C2 = LD(9);              // row2 (prefetch)

    // band0 (r0:3 -> r1:4): (0,3,4),(0,1,4),(1,4,5),(1,2,5),(2,5,6)
    EMIT(0, A0, B0, B1);
    EMIT(1, A0, A1, B1);
    EMIT(2, A1, B1, B2);
    EMIT(3, A1, A2, B2);
    EMIT(4, A2, B2, B3);

    // slide: A=row1(4), B=row2(3); prefetch row3(4)
    A0 = B0; A1 = B1; A2 = B2; A3 = B3;
    B0 = C0; B1 = C1; B2 = C2;
    C0 = LD(10); C1 = LD(11); C2 = LD(12); C3 = LD(13);
    // band1 (r1:4 -> r2:3): (3,4,7),(4,7,8),(4,5,8),(5,8,9),(5,6,9)
    EMIT(5, A0, A1, B0);
    EMIT(6, A1, B0, B1);
    EMIT(7, A1, A2, B1);
    EMIT(8, A2, B1, B2);
    EMIT(9, A2, A3, B2);

    // slide: A=row2(3), B=row3(4); prefetch row4(3)
    A0 = B0; A1 = B1; A2 = B2;
    B0 = C0; B1 = C1; B2 = C2; B3 = C3;
    C0 = LD(14); C1 = LD(15); C2 = LD(16);
    // band2 (r2:3 -> r3:4): (7,10,11),(7,8,11),(8,11,12),(8,9,12),(9,12,13)
    EMIT(10, A0, B0, B1);
    EMIT(11, A0, A1, B1);
    EMIT(12, A1, B1, B2);
    EMIT(13, A1, A2, B2);
    EMIT(14, A2, B2, B3);

    // slide: A=row3(4), B=row4(3); prefetch row5(4)
    A0 = B0; A1 = B1; A2 = B2; A3 = B3;
    B0 = C0; B1 = C1; B2 = C2;
    C0 = LD(17); C1 = LD(18); C2 = LD(19); C3 = LD(20);
    // band3 (r3:4 -> r4:3): (10,11,14),(11,14,15),(11,12,15),(12,15,16),(12,13,16)
    EMIT(15, A0, A1, B0);
    EMIT(16, A1, B0, B1);
    EMIT(17, A1, A2, B1);
    EMIT(18, A2, B1, B2);
    EMIT(19, A2, A3, B2);

    // slide: A=row4(3), B=row5(4); prefetch row6(3)
    A0 = B0; A1 = B1; A2 = B2;
    B0 = C0; B1 = C1; B2 = C2; B3 = C3;
    C0 = LD(21); C1 = LD(22); C2 = LD(23);
    // band4 (r4:3 -> r5:4): (14,17,18),(14,15,18),(15,18,19),(15,16,19),(16,19,20)
    EMIT(20, A0, B0, B1);
    EMIT(21, A0, A1, B1);
    EMIT(22, A1, B1, B2);
    EMIT(23, A1, A2, B2);
    EMIT(24, A2, B2, B3);

    // slide: A=row5(4), B=row6(3)
    A0 = B0; A1 = B1; A2 = B2; A3 = B3;
    B0 = C0; B1 = C1; B2 = C2;
    // band5 (r5:4 -> r6:3): (17,18,21),(18,21,22),(18,19,22),(19,22,23),(19,20,23)
    EMIT(25, A0, A1, B0);
    EMIT(26, A1, B0, B1);
    EMIT(27, A1, A2, B1);
    EMIT(28, A2, B1, B2);
    EMIT(29, A2, A3, B2);

#undef LD
#undef EMIT
}

extern "C" void kernel_launch(void* const* d_in, const int* in_sizes, int n_in,
                              void* d_out, int out_size) {
    const float4* x = (const float4*)d_in[0];
    float4* out = (float4*)d_out;

    dim3 block(TPB);
    dim3 grid(L4 / TPB, 64);  // (32, 64) = 2048 blocks
    tri_mean_kernel<<<grid, block>>>(x, out);
}

// round 11
// speedup vs baseline: 1.3979x; 1.0080x over previous
#include <cuda_runtime.h>
#include <cuda_bf16.h>

// out[b,c,t,l] = (x[b,c,i0,l] + x[b,c,i1,l] + x[b,c,i2,l]) / 3
// x: (32, 2, 24, 32768) fp32, out: (32, 2, 30, 32768) fp32
//
// R10 (one-band-ahead prefetch, 72.4us) extended to TWO-band lookahead:
// hold a 4-row window (rows k..k+3, <=14 float4 live). During band k's five
// __stcs stores, rows k+2 and k+3 loads are in flight (~7 reads/warp vs 3-4)
// -> deeper DRAM read queues while stores drain.
// launch_bounds(256,3): 85-reg budget, no spills. Occupancy is proven
// non-binding (R3 86% == R10 43% perf); queue depth is the lever.

#define NV 24
#define NT 30
#define L  32768
#define L4 (L / 4)
#define TPB 256

__global__ __launch_bounds__(TPB, 3)
void tri_mean_kernel(const float4* __restrict__ x, float4* __restrict__ out) {
    const int col = blockIdx.x * TPB + threadIdx.x;   // 0 .. L4-1
    const int bc  = blockIdx.y;                       // 0 .. 63

    const float4* __restrict__ xb = x   + (size_t)bc * NV * L4 + col;
    float4* __restrict__ ob       = out + (size_t)bc * NT * L4 + col;

    const float s = 1.0f / 3.0f;

#define LD(i)  xb[(size_t)(i) * L4]
#define EMIT(t, a, b, c) do {                        \
        float4 _r;                                   \
        _r.x = ((a).x + (b).x + (c).x) * s;          \
        _r.y = ((a).y + (b).y + (c).y) * s;          \
        _r.z = ((a).z + (b).z + (c).z) * s;          \
        _r.w = ((a).w + (b).w + (c).w) * s;          \
        __stcs(&ob[(size_t)(t) * L4], _r);           \
    } while (0)

    // 4-row window: A = row k, B = row k+1 (band k operands),
    //               C = row k+2, D = row k+3 (prefetched).
    float4 A0, A1, A2, A3;
    float4 B0, B1, B2, B3;
    float4 C0, C1, C2, C3;
    float4 D0, D1, D2, D3;

    // Rows (start,size): r0(0,3) r1(3,4) r2(7,3) r3(10,4) r4(14,3) r5(17,4) r6(21,3)
    A0 = LD(0);  A1 = LD(1);  A2 = LD(2);               // r0
    B0 = LD(3);  B1 = LD(4);  B2 = LD(5);  B3 = LD(6);  // r1
    C0 = LD(7);  C1 = LD(8);  C2 = LD(9);               // r2
    D0 = LD(10); D1 = LD(11); D2 = LD(12); D3 = LD(13); // r3

    // band0 (r0:3 -> r1:4): (0,3,4),(0,1,4),(1,4,5),(1,2,5),(2,5,6)
    EMIT(0, A0, B0, B1);
    EMIT(1, A0, A1, B1);
    EMIT(2, A1, B1, B2);
    EMIT(3, A1, A2, B2);
    EMIT(4, A2, B2, B3);

    // slide: A<-r1(4), B<-r2(3), C<-r3(4); prefetch D<-r4(3)
    A0 = B0; A1 = B1; A2 = B2; A3 = B3;
    B0 = C0; B1 = C1; B2 = C2;
    C0 = D0; C1 = D1; C2 = D2; C3 = D3;
    D0 = LD(14); D1 = LD(15); D2 = LD(16);
    // band1 (r1:4 -> r2:3): (3,4,7),(4,7,8),(4,5,8),(5,8,9),(5,6,9)
    EMIT(5, A0, A1, B0);
    EMIT(6, A1, B0, B1);
    EMIT(7, A1, A2, B1);
    EMIT(8, A2, B1, B2);
    EMIT(9, A2, A3, B2);

    // slide: A<-r2(3), B<-r3(4), C<-r4(3); prefetch D<-r5(4)
    A0 = B0; A1 = B1; A2 = B2;
    B0 = C0; B1 = C1; B2 = C2; B3 = C3;
    C0 = D0; C1 = D1; C2 = D2;
    D0 = LD(17); D1 = LD(18); D2 = LD(19); D3 = LD(20);
    // band2 (r2:3 -> r3:4): (7,10,11),(7,8,11),(8,11,12),(8,9,12),(9,12,13)
    EMIT(10, A0, B0, B1);
    EMIT(11, A0, A1, B1);
    EMIT(12, A1, B1, B2);
    EMIT(13, A1, A2, B2);
    EMIT(14, A2, B2, B3);

    // slide: A<-r3(4), B<-r4(3), C<-r5(4); prefetch D<-r6(3)
    A0 = B0; A1 = B1; A2 = B2; A3 = B3;
    B0 = C0; B1 = C1; B2 = C2;
    C0 = D0; C1 = D1; C2 = D2; C3 = D3;
    D0 = LD(21); D1 = LD(22); D2 = LD(23);
    // band3 (r3:4 -> r4:3): (10,11,14),(11,14,15),(11,12,15),(12,15,16),(12,13,16)
    EMIT(15, A0, A1, B0);
    EMIT(16, A1, B0, B1);
    EMIT(17, A1, A2, B1);
    EMIT(18, A2, B1, B2);
    EMIT(19, A2, A3, B2);

    // slide: A<-r4(3), B<-r5(4), C<-r6(3)
    A0 = B0; A1 = B1; A2 = B2;
    B0 = C0; B1 = C1; B2 = C2; B3 = C3;
    C0 = D0; C1 = D1; C2 = D2;
    // band4 (r4:3 -> r5:4): (14,17,18),(14,15,18),(15,18,19),(15,16,19),(16,19,20)
    EMIT(20, A0, B0, B1);
    EMIT(21, A0, A1, B1);
    EMIT(22, A1, B1, B2);
    EMIT(23, A1, A2, B2);
    EMIT(24, A2, B2, B3);

    // slide: A<-r5(4), B<-r6(3)
    A0 = B0; A1 = B1; A2 = B2; A3 = B3;
    B0 = C0; B1 = C1; B2 = C2;
    // band5 (r5:4 -> r6:3): (17,18,21),(18,21,22),(18,19,22),(19,22,23),(19,20,23)
    EMIT(25, A0, A1, B0);
    EMIT(26, A1, B0, B1);
    EMIT(27, A1, A2, B1);
    EMIT(28, A2, B1, B2);
    EMIT(29, A2, A3, B2);

#undef LD
#undef EMIT
}

extern "C" void kernel_launch(void* const* d_in, const int* in_sizes, int n_in,
                              void* d_out, int out_size) {
    const float4* x = (const float4*)d_in[0];
    float4* out = (float4*)d_out;

    dim3 block(TPB);
    dim3 grid(L4 / TPB, 64);  // (32, 64) = 2048 blocks
    tri_mean_kernel<<<grid, block>>>(x, out);
}

// round 12
// speedup vs baseline: 1.3992x; 1.0009x over previous
#include <cuda_runtime.h>
#include <cuda_bf16.h>

// out[b,c,t,l] = (x[b,c,i0,l] + x[b,c,i1,l] + x[b,c,i2,l]) / 3
// x: (32, 2, 24, 32768) fp32, out: (32, 2, 30, 32768) fp32
//
// THREE-band lookahead: 5-row sliding window (A..E). During band k's five
// __stcs stores, rows k+2..k+4 are in flight (~10 reads/warp).
// launch_bounds(256,2): 128-reg budget, no spills; 16 warps/SM.
// Terminal test of the lookahead gradient (R5->R10->R11 monotone tiny gains).

#define NV 24
#define NT 30
#define L  32768
#define L4 (L / 4)
#define TPB 256

__global__ __launch_bounds__(TPB, 2)
void tri_mean_kernel(const float4* __restrict__ x, float4* __restrict__ out) {
    const int col = blockIdx.x * TPB + threadIdx.x;   // 0 .. L4-1
    const int bc  = blockIdx.y;                       // 0 .. 63

    const float4* __restrict__ xb = x   + (size_t)bc * NV * L4 + col;
    float4* __restrict__ ob       = out + (size_t)bc * NT * L4 + col;

    const float s = 1.0f / 3.0f;

#define LD(i)  xb[(size_t)(i) * L4]
#define EMIT(t, a, b, c) do {                        \
        float4 _r;                                   \
        _r.x = ((a).x + (b).x + (c).x) * s;          \
        _r.y = ((a).y + (b).y + (c).y) * s;          \
        _r.z = ((a).z + (b).z + (c).z) * s;          \
        _r.w = ((a).w + (b).w + (c).w) * s;          \
        __stcs(&ob[(size_t)(t) * L4], _r);           \
    } while (0)

    // 5-row window: A = row k, B = row k+1 (band operands),
    //               C,D,E = rows k+2..k+4 (prefetched).
    float4 A0, A1, A2, A3;
    float4 B0, B1, B2, B3;
    float4 C0, C1, C2, C3;
    float4 D0, D1, D2, D3;
    float4 E0, E1, E2, E3;

    // Rows (start,size): r0(0,3) r1(3,4) r2(7,3) r3(10,4) r4(14,3) r5(17,4) r6(21,3)
    A0 = LD(0);  A1 = LD(1);  A2 = LD(2);               // r0
    B0 = LD(3);  B1 = LD(4);  B2 = LD(5);  B3 = LD(6);  // r1
    C0 = LD(7);  C1 = LD(8);  C2 = LD(9);               // r2
    D0 = LD(10); D1 = LD(11); D2 = LD(12); D3 = LD(13); // r3
    E0 = LD(14); E1 = LD(15); E2 = LD(16);              // r4

    // band0 (r0:3 -> r1:4): (0,3,4),(0,1,4),(1,4,5),(1,2,5),(2,5,6)
    EMIT(0, A0, B0, B1);
    EMIT(1, A0, A1, B1);
    EMIT(2, A1, B1, B2);
    EMIT(3, A1, A2, B2);
    EMIT(4, A2, B2, B3);

    // slide; prefetch r5(4) into E
    A0 = B0; A1 = B1; A2 = B2; A3 = B3;   // A<-r1(4)
    B0 = C0; B1 = C1; B2 = C2;            // B<-r2(3)
    C0 = D0; C1 = D1; C2 = D2; C3 = D3;   // C<-r3(4)
    D0 = E0; D1 = E1; D2 = E2;            // D<-r4(3)
    E0 = LD(17); E1 = LD(18); E2 = LD(19); E3 = LD(20); // E<-r5(4)
    // band1 (r1:4 -> r2:3): (3,4,7),(4,7,8),(4,5,8),(5,8,9),(5,6,9)
    EMIT(5, A0, A1, B0);
    EMIT(6, A1, B0, B1);
    EMIT(7, A1, A2, B1);
    EMIT(8, A2, B1, B2);
    EMIT(9, A2, A3, B2);

    // slide; prefetch r6(3) into E
    A0 = B0; A1 = B1; A2 = B2;            // A<-r2(3)
    B0 = C0; B1 = C1; B2 = C2; B3 = C3;   // B<-r3(4)
    C0 = D0; C1 = D1; C2 = D2;            // C<-r4(3)
    D0 = E0; D1 = E1; D2 = E2; D3 = E3;   // D<-r5(4)
    E0 = LD(21); E1 = LD(22); E2 = LD(23);              // E<-r6(3)
    // band2 (r2:3 -> r3:4): (7,10,11),(7,8,11),(8,11,12),(8,9,12),(9,12,13)
    EMIT(10, A0, B0, B1);
    EMIT(11, A0, A1, B1);
    EMIT(12, A1, B1, B2);
    EMIT(13, A1, A2, B2);
    EMIT(14, A2, B2, B3);

    // slide (no more loads)
    A0 = B0; A1 = B1; A2 = B2; A3 = B3;   // A<-r3(4)
    B0 = C0; B1 = C1; B2 = C2;            // B<-r4(3)
    C0 = D0; C1 = D1; C2 = D2; C3 = D3;   // C<-r5(4)
    D0 = E0; D1 = E1; D2 = E2;            // D<-r6(3)
    // band3 (r3:4 -> r4:3): (10,11,14),(11,14,15),(11,12,15),(12,15,16),(12,13,16)
    EMIT(15, A0, A1, B0);
    EMIT(16, A1, B0, B1);
    EMIT(17, A1, A2, B1);
    EMIT(18, A2, B1, B2);
    EMIT(19, A2, A3, B2);

    // slide
    A0 = B0; A1 = B1; A2 = B2;            // A<-r4(3)
    B0 = C0; B1 = C1; B2 = C2; B3 = C3;   // B<-r5(4)
    C0 = D0; C1 = D1; C2 = D2;            // C<-r6(3)
    // band4 (r4:3 -> r5:4): (14,17,18),(14,15,18),(15,18,19),(15,16,19),(16,19,20)
    EMIT(20, A0, B0, B1);
    EMIT(21, A0, A1, B1);
    EMIT(22, A1, B1, B2);
    EMIT(23, A1, A2, B2);
    EMIT(24, A2, B2, B3);

    // slide
    A0 = B0; A1 = B1; A2 = B2; A3 = B3;   // A<-r5(4)
    B0 = C0; B1 = C1; B2 = C2;            // B<-r6(3)
    // band5 (r5:4 -> r6:3): (17,18,21),(18,21,22),(18,19,22),(19,22,23),(19,20,23)
    EMIT(25, A0, A1, B0);
    EMIT(26, A1, B0, B1);
    EMIT(27, A1, A2, B1);
    EMIT(28, A2, B1, B2);
    EMIT(29, A2, A3, B2);

#undef LD
#undef EMIT
}

extern "C" void kernel_launch(void* const* d_in, const int* in_sizes, int n_in,
                              void* d_out, int out_size) {
    const float4* x = (const float4*)d_in[0];
    float4* out = (float4*)d_out;

    dim3 block(TPB);
    dim3 grid(L4 / TPB, 64);  // (32, 64) = 2048 blocks
    tri_mean_kernel<<<grid, block>>>(x, out);
}